// round 4
// baseline (speedup 1.0000x reference)
#include <cuda_runtime.h>
#include <math.h>

#define BATCH 2
#define SEQ   2048
#define HIDD  1024
#define NH    16
#define HD    64
#define OP    (NH*HD)        // 1024
#define NTOT  (3*OP)         // 3072
#define MTOT  (BATCH*SEQ)    // 4096

// Scratch for projected Q/K/V in [B, NH, S, HD] layout (16 MB each).
__device__ float g_Q[BATCH*NH*SEQ*HD];
__device__ float g_K[BATCH*NH*SEQ*HD];
__device__ float g_V[BATCH*NH*SEQ*HD];

// ---------------------------------------------------------------------------
// Kernel 1: fused QKV projection.  X[4096,1024] @ W[1024,3072] + bias,
// scattered into g_Q/g_K/g_V head-split layout.
// 128x128 block tile, BK=16, 256 threads, 8x8 per-thread microtile.
// ---------------------------------------------------------------------------
__global__ void __launch_bounds__(256) proj_kernel(
    const float* __restrict__ X,
    const float* __restrict__ Wqk, const float* __restrict__ bqk,
    const float* __restrict__ Wv,  const float* __restrict__ bv)
{
    __shared__ float As[16][128];   // transposed A tile: As[k][m]
    __shared__ float Bs[16][128];   // Bs[k][n]

    const int tid = threadIdx.x;
    const int tx = tid & 15;        // 0..15 -> n
    const int ty = tid >> 4;        // 0..15 -> m
    const int mBase = blockIdx.y * 128;
    const int nBase = blockIdx.x * 128;

    float acc[8][8];
    #pragma unroll
    for (int i = 0; i < 8; i++)
        #pragma unroll
        for (int j = 0; j < 8; j++) acc[i][j] = 0.f;

    for (int k0 = 0; k0 < HIDD; k0 += 16) {
        // load A tile: 128 rows x 16 k = 512 float4
        #pragma unroll
        for (int i = 0; i < 2; i++) {
            int idx = tid + i * 256;
            int row = idx >> 2;
            int kq  = (idx & 3) * 4;
            float4 v = *reinterpret_cast<const float4*>(
                &X[(size_t)(mBase + row) * HIDD + k0 + kq]);
            As[kq + 0][row] = v.x;
            As[kq + 1][row] = v.y;
            As[kq + 2][row] = v.z;
            As[kq + 3][row] = v.w;
        }
        // load B tile: 16 k x 128 n = 512 float4
        #pragma unroll
        for (int i = 0; i < 2; i++) {
            int idx = tid + i * 256;
            int kk  = idx >> 5;
            int col = (idx & 31) * 4;
            int n   = nBase + col;
            float4 v;
            if (n < 2 * OP)
                v = *reinterpret_cast<const float4*>(
                    &Wqk[(size_t)(k0 + kk) * (2 * OP) + n]);
            else
                v = *reinterpret_cast<const float4*>(
                    &Wv[(size_t)(k0 + kk) * OP + (n - 2 * OP)]);
            *reinterpret_cast<float4*>(&Bs[kk][col]) = v;
        }
        __syncthreads();

        #pragma unroll
        for (int kk = 0; kk < 16; kk++) {
            float ar[8], br[8];
            #pragma unroll
            for (int i = 0; i < 8; i++) ar[i] = As[kk][ty * 8 + i];
            #pragma unroll
            for (int j = 0; j < 8; j++) br[j] = Bs[kk][tx * 8 + j];
            #pragma unroll
            for (int i = 0; i < 8; i++)
                #pragma unroll
                for (int j = 0; j < 8; j++)
                    acc[i][j] += ar[i] * br[j];
        }
        __syncthreads();
    }

    // epilogue: add bias, scatter to Q/K/V in [B,NH,S,HD]
    #pragma unroll
    for (int i = 0; i < 8; i++) {
        int m = mBase + ty * 8 + i;
        int b = m / SEQ;
        int s = m % SEQ;
        #pragma unroll
        for (int j = 0; j < 8; j++) {
            int n = nBase + tx * 8 + j;
            float bias = (n < 2 * OP) ? bqk[n] : bv[n - 2 * OP];
            float val = acc[i][j] + bias;
            float* buf;
            int local;
            if (n < OP)            { buf = g_Q; local = n; }
            else if (n < 2 * OP)   { buf = g_K; local = n - OP; }
            else                   { buf = g_V; local = n - 2 * OP; }
            int h = local / HD;
            int d = local % HD;
            buf[(((size_t)(b * NH + h)) * SEQ + s) * HD + d] = val;
        }
    }
}

// ---------------------------------------------------------------------------
// Kernel 2: causal flash attention, fp32.
// One CTA per (64-query tile, head, batch). 64-wide KV tiles, online softmax.
// 256 threads, each owns a 4x4 score/output microtile.
// ---------------------------------------------------------------------------
#define QT 64
#define KT 64
// smem layout (floats): Qs[64*64] | Ps[64*64] | Ks[64*65] | Vs[64*65]
#define SME_QS  0
#define SME_PS  (64*64)
#define SME_KS  (2*64*64)
#define SME_VS  (2*64*64 + 64*65)
#define SMEM_FLOATS (2*64*64 + 2*64*65)

__global__ void __launch_bounds__(256) attn_kernel(float* __restrict__ out)
{
    extern __shared__ float smem[];
    float* Qs = smem + SME_QS;
    float* Ps = smem + SME_PS;
    float* Ks = smem + SME_KS;
    float* Vs = smem + SME_VS;

    const int tid = threadIdx.x;
    const int tx = tid & 15;    // key-col group
    const int ty = tid >> 4;    // query-row group
    const int qt = gridDim.x - 1 - blockIdx.x;  // heavy tiles launch first
    const int h  = blockIdx.y;
    const int b  = blockIdx.z;
    const size_t headBase = ((size_t)(b * NH + h)) * SEQ * HD;
    const int qBase = qt * QT;
    const int r0 = ty * 4;
    const int c0 = tx * 4;

    // load Q tile (64x64)
    #pragma unroll
    for (int i = 0; i < 16; i++) {
        int idx = tid + i * 256;
        int r = idx >> 6, d = idx & 63;
        Qs[r * 64 + d] = g_Q[headBase + (size_t)(qBase + r) * HD + d];
    }

    float o[4][4];
    float mrow[4], lrow[4];
    #pragma unroll
    for (int i = 0; i < 4; i++) {
        mrow[i] = -1e30f; lrow[i] = 0.f;
        #pragma unroll
        for (int j = 0; j < 4; j++) o[i][j] = 0.f;
    }

    const float scale = 0.125f;  // 1/sqrt(64)

    for (int kt = 0; kt <= qt; kt++) {
        const int kBase = kt * KT;
        __syncthreads();   // previous iteration's PV readers done
        #pragma unroll
        for (int i = 0; i < 16; i++) {
            int idx = tid + i * 256;
            int r = idx >> 6, d = idx & 63;
            size_t gi = headBase + (size_t)(kBase + r) * HD + d;
            Ks[r * 65 + d] = g_K[gi];
            Vs[r * 65 + d] = g_V[gi];
        }
        __syncthreads();

        // S = Q K^T
        float sc[4][4];
        #pragma unroll
        for (int i = 0; i < 4; i++)
            #pragma unroll
            for (int j = 0; j < 4; j++) sc[i][j] = 0.f;

        #pragma unroll 8
        for (int k = 0; k < 64; k++) {
            float qv[4], kv[4];
            #pragma unroll
            for (int i = 0; i < 4; i++) qv[i] = Qs[(r0 + i) * 64 + k];
            #pragma unroll
            for (int j = 0; j < 4; j++) kv[j] = Ks[(c0 + j) * 65 + k];
            #pragma unroll
            for (int i = 0; i < 4; i++)
                #pragma unroll
                for (int j = 0; j < 4; j++)
                    sc[i][j] += qv[i] * kv[j];
        }

        const bool diag = (kt == qt);
        #pragma unroll
        for (int i = 0; i < 4; i++)
            #pragma unroll
            for (int j = 0; j < 4; j++) {
                float v = sc[i][j] * scale;
                if (diag && (kBase + c0 + j) > (qBase + r0 + i)) v = -1e30f;
                sc[i][j] = v;
            }

        // online softmax: row max + row sum across 16 tx threads (shfl, width 16)
        float alpha[4];
        #pragma unroll
        for (int i = 0; i < 4; i++) {
            float v = fmaxf(fmaxf(sc[i][0], sc[i][1]), fmaxf(sc[i][2], sc[i][3]));
            #pragma unroll
            for (int off = 8; off > 0; off >>= 1)
                v = fmaxf(v, __shfl_xor_sync(0xFFFFFFFFu, v, off));
            float mnew = fmaxf(mrow[i], v);
            alpha[i] = __expf(mrow[i] - mnew);
            mrow[i] = mnew;
        }
        #pragma unroll
        for (int i = 0; i < 4; i++) {
            float s = 0.f;
            #pragma unroll
            for (int j = 0; j < 4; j++) {
                float p = __expf(sc[i][j] - mrow[i]);
                sc[i][j] = p;
                s += p;
            }
            #pragma unroll
            for (int off = 8; off > 0; off >>= 1)
                s += __shfl_xor_sync(0xFFFFFFFFu, s, off);
            lrow[i] = lrow[i] * alpha[i] + s;
        }

        // rescale O, publish P
        #pragma unroll
        for (int i = 0; i < 4; i++)
            #pragma unroll
            for (int j = 0; j < 4; j++) {
                o[i][j] *= alpha[i];
                Ps[(r0 + i) * 64 + (c0 + j)] = sc[i][j];
            }
        __syncthreads();

        // O += P V
        #pragma unroll 8
        for (int k = 0; k < 64; k++) {
            float pv[4], vv[4];
            #pragma unroll
            for (int i = 0; i < 4; i++) pv[i] = Ps[(r0 + i) * 64 + k];
            #pragma unroll
            for (int j = 0; j < 4; j++) vv[j] = Vs[k * 65 + c0 + j];
            #pragma unroll
            for (int i = 0; i < 4; i++)
                #pragma unroll
                for (int j = 0; j < 4; j++)
                    o[i][j] += pv[i] * vv[j];
        }
    }

    // normalize + write: out[b][s][h*HD + d]
    #pragma unroll
    for (int i = 0; i < 4; i++) {
        int s = qBase + r0 + i;
        float inv = 1.f / lrow[i];
        #pragma unroll
        for (int j = 0; j < 4; j++) {
            out[((size_t)b * SEQ + s) * OP + h * HD + c0 + j] = o[i][j] * inv;
        }
    }
}

// ---------------------------------------------------------------------------
extern "C" void kernel_launch(void* const* d_in, const int* in_sizes, int n_in,
                              void* d_out, int out_size)
{
    const float* X   = (const float*)d_in[0];
    const float* Wqk = (const float*)d_in[1];
    const float* bqk = (const float*)d_in[2];
    const float* Wv  = (const float*)d_in[3];
    const float* bv  = (const float*)d_in[4];
    float* out = (float*)d_out;

    (void)in_sizes; (void)n_in; (void)out_size;

    dim3 g1(NTOT / 128, MTOT / 128);   // (24, 32)
    proj_kernel<<<g1, 256>>>(X, Wqk, bqk, Wv, bv);

    const int smemBytes = SMEM_FLOATS * sizeof(float);  // ~66 KB
    cudaFuncSetAttribute(attn_kernel,
                         cudaFuncAttributeMaxDynamicSharedMemorySize, smemBytes);
    dim3 g2(SEQ / QT, NH, BATCH);      // (32, 16, 2)
    attn_kernel<<<g2, 256, smemBytes>>>(out);
}

// round 6
// speedup vs baseline: 1.4928x; 1.4928x over previous
#include <cuda_runtime.h>
#include <cuda_bf16.h>
#include <stdint.h>
#include <math.h>

#define BATCH 2
#define SEQ   2048
#define HIDD  1024
#define NH    16
#define HD    64
#define OP    (NH*HD)        // 1024
#define NTOT  (3*OP)         // 3072
#define MTOT  (BATCH*SEQ)    // 4096

// Scratch: projected Q/K/V in [B, NH, S, HD] (fp32) + bf16 hi/lo operand copies.
__device__ float g_Q[BATCH*NH*SEQ*HD];
__device__ float g_K[BATCH*NH*SEQ*HD];
__device__ float g_V[BATCH*NH*SEQ*HD];
__device__ __nv_bfloat16 g_Xh[MTOT*HIDD];
__device__ __nv_bfloat16 g_Xl[MTOT*HIDD];
__device__ __nv_bfloat16 g_Wh[NTOT*HIDD];   // W transposed: [n][k]
__device__ __nv_bfloat16 g_Wl[NTOT*HIDD];

__device__ __forceinline__ void hilo(float x, __nv_bfloat16& h, __nv_bfloat16& l) {
    h = __float2bfloat16(x);
    l = __float2bfloat16(x - __bfloat162float(h));
}

// ---------------------------------------------------------------------------
// Convert X -> hi/lo bf16 (same [m][k] layout).
// ---------------------------------------------------------------------------
__global__ void __launch_bounds__(256) cvtX_kernel(const float* __restrict__ X)
{
    int idx = (blockIdx.x * 256 + threadIdx.x) * 4;
    float4 v = *reinterpret_cast<const float4*>(&X[idx]);
    __nv_bfloat16 h[4], l[4];
    hilo(v.x, h[0], l[0]); hilo(v.y, h[1], l[1]);
    hilo(v.z, h[2], l[2]); hilo(v.w, h[3], l[3]);
    *reinterpret_cast<uint2*>(&g_Xh[idx]) = *reinterpret_cast<uint2*>(h);
    *reinterpret_cast<uint2*>(&g_Xl[idx]) = *reinterpret_cast<uint2*>(l);
}

// ---------------------------------------------------------------------------
// Transpose + convert W: Wqk[1024][2048] / Wv[1024][1024] -> Wt[hi/lo][n][k].
// 32x32 tiles, 256 threads (32 x, 8 y).
// ---------------------------------------------------------------------------
__global__ void __launch_bounds__(256) cvtW_kernel(
    const float* __restrict__ Wqk, const float* __restrict__ Wv)
{
    __shared__ float s[32][33];
    const int tx = threadIdx.x & 31;
    const int ty = threadIdx.x >> 5;          // 0..7
    const int nTile = blockIdx.x * 32;        // 0..3071
    const int kTile = blockIdx.y * 32;        // 0..1023

    #pragma unroll
    for (int r = 0; r < 4; r++) {
        int k = kTile + ty + r * 8;
        int n = nTile + tx;
        float v = (n < 2 * OP) ? Wqk[(size_t)k * (2 * OP) + n]
                               : Wv[(size_t)k * OP + (n - 2 * OP)];
        s[ty + r * 8][tx] = v;
    }
    __syncthreads();
    #pragma unroll
    for (int r = 0; r < 4; r++) {
        int n = nTile + ty + r * 8;
        int k = kTile + tx;
        __nv_bfloat16 h, l;
        hilo(s[tx][ty + r * 8], h, l);
        g_Wh[(size_t)n * HIDD + k] = h;
        g_Wl[(size_t)n * HIDD + k] = l;
    }
}

// ---------------------------------------------------------------------------
// Kernel: QKV projection on HMMA (mma.sync m16n8k16 bf16, 2-term split).
// 128x128 CTA tile, BK=32, 8 warps, warp tile 32m x 64n.
// ---------------------------------------------------------------------------
#define LDX4(r, a) \
    asm volatile("ldmatrix.sync.aligned.m8n8.x4.shared.b16 {%0,%1,%2,%3}, [%4];" \
        : "=r"((r)[0]), "=r"((r)[1]), "=r"((r)[2]), "=r"((r)[3]) : "r"(a))

#define MMA16816(c, a, b0_, b1_) \
    asm volatile("mma.sync.aligned.m16n8k16.row.col.f32.bf16.bf16.f32 " \
        "{%0,%1,%2,%3},{%4,%5,%6,%7},{%8,%9},{%0,%1,%2,%3};" \
        : "+f"((c)[0]), "+f"((c)[1]), "+f"((c)[2]), "+f"((c)[3]) \
        : "r"((a)[0]), "r"((a)[1]), "r"((a)[2]), "r"((a)[3]), \
          "r"(b0_), "r"(b1_))

__device__ __forceinline__ uint32_t smem_u32(const void* p) {
    uint32_t a;
    asm("{ .reg .u64 t; cvta.to.shared.u64 t, %1; cvt.u32.u64 %0, t; }"
        : "=r"(a) : "l"(p));
    return a;
}

// smem rows: 32 bf16 (64B) padded to 40 bf16 (80B) -> conflict-free ldmatrix.
#define SROW 40

__device__ __forceinline__ void qkv_store2(int m, int n, float v0, float v1,
                                           const float* bqk, const float* bv)
{
    int b = m >> 11;           // /SEQ
    int s = m & (SEQ - 1);
    const float* bias = (n < 2 * OP) ? &bqk[n] : &bv[n - 2 * OP];
    float* buf; int loc;
    if (n < OP)          { buf = g_Q; loc = n; }
    else if (n < 2 * OP) { buf = g_K; loc = n - OP; }
    else                 { buf = g_V; loc = n - 2 * OP; }
    int h = loc >> 6, dd = loc & 63;
    float2 w = make_float2(v0 + bias[0], v1 + bias[1]);
    *reinterpret_cast<float2*>(
        &buf[(((size_t)(b * NH + h)) * SEQ + s) * HD + dd]) = w;
}

__global__ void __launch_bounds__(256, 2) proj3_kernel(
    const float* __restrict__ bqk, const float* __restrict__ bv)
{
    __shared__ __align__(16) __nv_bfloat16 sAh[128 * SROW];
    __shared__ __align__(16) __nv_bfloat16 sAl[128 * SROW];
    __shared__ __align__(16) __nv_bfloat16 sBh[128 * SROW];
    __shared__ __align__(16) __nv_bfloat16 sBl[128 * SROW];

    const int tid  = threadIdx.x;
    const int lane = tid & 31;
    const int wid  = tid >> 5;
    const int warpM = wid & 3;      // 4 m-tiles of 32
    const int warpN = wid >> 2;     // 2 n-tiles of 64
    const int mBase = blockIdx.y * 128;
    const int nBase = blockIdx.x * 128;

    const uint32_t uAh = smem_u32(sAh), uAl = smem_u32(sAl);
    const uint32_t uBh = smem_u32(sBh), uBl = smem_u32(sBl);

    float acc[2][8][4];
    #pragma unroll
    for (int i = 0; i < 2; i++)
        #pragma unroll
        for (int j = 0; j < 8; j++)
            #pragma unroll
            for (int q = 0; q < 4; q++) acc[i][j][q] = 0.f;

    // ldmatrix lane addressing (bytes), precomputed per-thread offsets
    const uint32_t aRowOff = (uint32_t)(warpM * 32 + (lane & 15)) * (SROW * 2)
                           + (lane >> 4) * 16;
    const uint32_t bRowSel = (uint32_t)((lane >> 4) * 8 + (lane & 7));
    const uint32_t bHalf   = ((lane >> 3) & 1) * 16;

    for (int c = 0; c < 32; ++c) {
        const int k0 = c * 32;
        __syncthreads();
        #pragma unroll
        for (int i = 0; i < 2; i++) {
            int idx = tid + i * 256;
            int row = idx >> 2;
            int cg  = idx & 3;
            int so  = row * SROW + cg * 8;
            size_t ga = (size_t)(mBase + row) * HIDD + k0 + cg * 8;
            size_t gb = (size_t)(nBase + row) * HIDD + k0 + cg * 8;
            *reinterpret_cast<uint4*>(&sAh[so]) = *reinterpret_cast<const uint4*>(&g_Xh[ga]);
            *reinterpret_cast<uint4*>(&sAl[so]) = *reinterpret_cast<const uint4*>(&g_Xl[ga]);
            *reinterpret_cast<uint4*>(&sBh[so]) = *reinterpret_cast<const uint4*>(&g_Wh[gb]);
            *reinterpret_cast<uint4*>(&sBl[so]) = *reinterpret_cast<const uint4*>(&g_Wl[gb]);
        }
        __syncthreads();

        #pragma unroll
        for (int ks = 0; ks < 2; ks++) {
            const uint32_t kOff = ks * 32;   // 16 bf16 = 32 bytes
            uint32_t ah[2][4], al[2][4];
            #pragma unroll
            for (int mi = 0; mi < 2; mi++) {
                uint32_t off = aRowOff + (uint32_t)(mi * 16) * (SROW * 2) + kOff;
                LDX4(ah[mi], uAh + off);
                LDX4(al[mi], uAl + off);
            }
            #pragma unroll
            for (int g = 0; g < 4; g++) {     // n16 groups within warp's 64
                uint32_t nrow = (uint32_t)(warpN * 64 + g * 16) + bRowSel;
                uint32_t off = nrow * (SROW * 2) + kOff + bHalf;
                uint32_t bh[4], bl[4];
                LDX4(bh, uBh + off);
                LDX4(bl, uBl + off);
                #pragma unroll
                for (int mi = 0; mi < 2; mi++) {
                    MMA16816(acc[mi][2 * g],     ah[mi], bh[0], bh[1]);
                    MMA16816(acc[mi][2 * g],     ah[mi], bl[0], bl[1]);
                    MMA16816(acc[mi][2 * g],     al[mi], bh[0], bh[1]);
                    MMA16816(acc[mi][2 * g + 1], ah[mi], bh[2], bh[3]);
                    MMA16816(acc[mi][2 * g + 1], ah[mi], bl[2], bl[3]);
                    MMA16816(acc[mi][2 * g + 1], al[mi], bh[2], bh[3]);
                }
            }
        }
    }

    // Epilogue: fragment -> global with bias + head-split scatter.
    const int mW = mBase + warpM * 32 + (lane >> 2);
    const int nW = nBase + warpN * 64 + (lane & 3) * 2;
    #pragma unroll
    for (int mi = 0; mi < 2; mi++) {
        int r0 = mW + mi * 16;
        #pragma unroll
        for (int g = 0; g < 8; g++) {
            int col = nW + g * 8;
            qkv_store2(r0,     col, acc[mi][g][0], acc[mi][g][1], bqk, bv);
            qkv_store2(r0 + 8, col, acc[mi][g][2], acc[mi][g][3], bqk, bv);
        }
    }
}

// ---------------------------------------------------------------------------
// Causal flash attention, fp32 (unchanged — near fp32 issue ceiling).
// ---------------------------------------------------------------------------
#define QT 64
#define KT 64
#define SME_QS  0
#define SME_PS  (64*64)
#define SME_KS  (2*64*64)
#define SME_VS  (2*64*64 + 64*65)
#define SMEM_FLOATS (2*64*64 + 2*64*65)

__global__ void __launch_bounds__(256) attn_kernel(float* __restrict__ out)
{
    extern __shared__ float fsmem[];
    float* Qs = fsmem + SME_QS;
    float* Ps = fsmem + SME_PS;
    float* Ks = fsmem + SME_KS;
    float* Vs = fsmem + SME_VS;

    const int tid = threadIdx.x;
    const int tx = tid & 15;
    const int ty = tid >> 4;
    const int qt = gridDim.x - 1 - blockIdx.x;
    const int h  = blockIdx.y;
    const int b  = blockIdx.z;
    const size_t headBase = ((size_t)(b * NH + h)) * SEQ * HD;
    const int qBase = qt * QT;
    const int r0 = ty * 4;
    const int c0 = tx * 4;

    #pragma unroll
    for (int i = 0; i < 16; i++) {
        int idx = tid + i * 256;
        int r = idx >> 6, d = idx & 63;
        Qs[r * 64 + d] = g_Q[headBase + (size_t)(qBase + r) * HD + d];
    }

    float o[4][4];
    float mrow[4], lrow[4];
    #pragma unroll
    for (int i = 0; i < 4; i++) {
        mrow[i] = -1e30f; lrow[i] = 0.f;
        #pragma unroll
        for (int j = 0; j < 4; j++) o[i][j] = 0.f;
    }

    const float scale = 0.125f;

    for (int kt = 0; kt <= qt; kt++) {
        const int kBase = kt * KT;
        __syncthreads();
        #pragma unroll
        for (int i = 0; i < 16; i++) {
            int idx = tid + i * 256;
            int r = idx >> 6, d = idx & 63;
            size_t gi = headBase + (size_t)(kBase + r) * HD + d;
            Ks[r * 65 + d] = g_K[gi];
            Vs[r * 65 + d] = g_V[gi];
        }
        __syncthreads();

        float sc[4][4];
        #pragma unroll
        for (int i = 0; i < 4; i++)
            #pragma unroll
            for (int j = 0; j < 4; j++) sc[i][j] = 0.f;

        #pragma unroll 8
        for (int k = 0; k < 64; k++) {
            float qv[4], kv[4];
            #pragma unroll
            for (int i = 0; i < 4; i++) qv[i] = Qs[(r0 + i) * 64 + k];
            #pragma unroll
            for (int j = 0; j < 4; j++) kv[j] = Ks[(c0 + j) * 65 + k];
            #pragma unroll
            for (int i = 0; i < 4; i++)
                #pragma unroll
                for (int j = 0; j < 4; j++)
                    sc[i][j] += qv[i] * kv[j];
        }

        const bool diag = (kt == qt);
        #pragma unroll
        for (int i = 0; i < 4; i++)
            #pragma unroll
            for (int j = 0; j < 4; j++) {
                float v = sc[i][j] * scale;
                if (diag && (kBase + c0 + j) > (qBase + r0 + i)) v = -1e30f;
                sc[i][j] = v;
            }

        float alpha[4];
        #pragma unroll
        for (int i = 0; i < 4; i++) {
            float v = fmaxf(fmaxf(sc[i][0], sc[i][1]), fmaxf(sc[i][2], sc[i][3]));
            #pragma unroll
            for (int off = 8; off > 0; off >>= 1)
                v = fmaxf(v, __shfl_xor_sync(0xFFFFFFFFu, v, off));
            float mnew = fmaxf(mrow[i], v);
            alpha[i] = __expf(mrow[i] - mnew);
            mrow[i] = mnew;
        }
        #pragma unroll
        for (int i = 0; i < 4; i++) {
            float s = 0.f;
            #pragma unroll
            for (int j = 0; j < 4; j++) {
                float p = __expf(sc[i][j] - mrow[i]);
                sc[i][j] = p;
                s += p;
            }
            #pragma unroll
            for (int off = 8; off > 0; off >>= 1)
                s += __shfl_xor_sync(0xFFFFFFFFu, s, off);
            lrow[i] = lrow[i] * alpha[i] + s;
        }

        #pragma unroll
        for (int i = 0; i < 4; i++)
            #pragma unroll
            for (int j = 0; j < 4; j++) {
                o[i][j] *= alpha[i];
                Ps[(r0 + i) * 64 + (c0 + j)] = sc[i][j];
            }
        __syncthreads();

        #pragma unroll 8
        for (int k = 0; k < 64; k++) {
            float pv[4], vv[4];
            #pragma unroll
            for (int i = 0; i < 4; i++) pv[i] = Ps[(r0 + i) * 64 + k];
            #pragma unroll
            for (int j = 0; j < 4; j++) vv[j] = Vs[k * 65 + c0 + j];
            #pragma unroll
            for (int i = 0; i < 4; i++)
                #pragma unroll
                for (int j = 0; j < 4; j++)
                    o[i][j] += pv[i] * vv[j];
        }
    }

    #pragma unroll
    for (int i = 0; i < 4; i++) {
        int s = qBase + r0 + i;
        float inv = 1.f / lrow[i];
        #pragma unroll
        for (int j = 0; j < 4; j++) {
            out[((size_t)b * SEQ + s) * OP + h * HD + c0 + j] = o[i][j] * inv;
        }
    }
}

// ---------------------------------------------------------------------------
extern "C" void kernel_launch(void* const* d_in, const int* in_sizes, int n_in,
                              void* d_out, int out_size)
{
    const float* X   = (const float*)d_in[0];
    const float* Wqk = (const float*)d_in[1];
    const float* bqk = (const float*)d_in[2];
    const float* Wv  = (const float*)d_in[3];
    const float* bv  = (const float*)d_in[4];
    float* out = (float*)d_out;

    (void)in_sizes; (void)n_in; (void)out_size;

    cvtX_kernel<<<MTOT * HIDD / 1024, 256>>>(X);
    cvtW_kernel<<<dim3(NTOT / 32, HIDD / 32), 256>>>(Wqk, Wv);

    dim3 g1(NTOT / 128, MTOT / 128);   // (24, 32)
    proj3_kernel<<<g1, 256>>>(bqk, bv);

    const int smemBytes = SMEM_FLOATS * sizeof(float);  // ~66 KB
    cudaFuncSetAttribute(attn_kernel,
                         cudaFuncAttributeMaxDynamicSharedMemorySize, smemBytes);
    dim3 g2(SEQ / QT, NH, BATCH);      // (32, 16, 2)
    attn_kernel<<<g2, 256, smemBytes>>>(out);
}

// round 7
// speedup vs baseline: 2.8910x; 1.9366x over previous
#include <cuda_runtime.h>
#include <cuda_bf16.h>
#include <stdint.h>
#include <math.h>

#define BATCH 2
#define SEQ   2048
#define HIDD  1024
#define NH    16
#define HD    64
#define OP    (NH*HD)        // 1024
#define NTOT  (3*OP)         // 3072
#define MTOT  (BATCH*SEQ)    // 4096

// bf16 hi/lo operand copies (projection inputs)
__device__ __nv_bfloat16 g_Xh[MTOT*HIDD];
__device__ __nv_bfloat16 g_Xl[MTOT*HIDD];
__device__ __nv_bfloat16 g_Wh[NTOT*HIDD];   // W transposed: [n][k]
__device__ __nv_bfloat16 g_Wl[NTOT*HIDD];
// projected Q/K/V as bf16 hi/lo, [B, NH, S, HD]; Q pre-scaled by 1/8
__device__ __nv_bfloat16 g_Qh[BATCH*NH*SEQ*HD];
__device__ __nv_bfloat16 g_Ql[BATCH*NH*SEQ*HD];
__device__ __nv_bfloat16 g_Kh[BATCH*NH*SEQ*HD];
__device__ __nv_bfloat16 g_Kl[BATCH*NH*SEQ*HD];
__device__ __nv_bfloat16 g_Vh[BATCH*NH*SEQ*HD];
__device__ __nv_bfloat16 g_Vl[BATCH*NH*SEQ*HD];

__device__ __forceinline__ void hilo(float x, __nv_bfloat16& h, __nv_bfloat16& l) {
    h = __float2bfloat16(x);
    l = __float2bfloat16(x - __bfloat162float(h));
}
__device__ __forceinline__ uint32_t pk2(__nv_bfloat16 a, __nv_bfloat16 b) {
    __nv_bfloat162 t; t.x = a; t.y = b;
    return *reinterpret_cast<uint32_t*>(&t);
}

// ---------------------------------------------------------------------------
// Convert X -> hi/lo bf16 (same [m][k] layout).
// ---------------------------------------------------------------------------
__global__ void __launch_bounds__(256) cvtX_kernel(const float* __restrict__ X)
{
    int idx = (blockIdx.x * 256 + threadIdx.x) * 4;
    float4 v = *reinterpret_cast<const float4*>(&X[idx]);
    __nv_bfloat16 h[4], l[4];
    hilo(v.x, h[0], l[0]); hilo(v.y, h[1], l[1]);
    hilo(v.z, h[2], l[2]); hilo(v.w, h[3], l[3]);
    *reinterpret_cast<uint2*>(&g_Xh[idx]) = *reinterpret_cast<uint2*>(h);
    *reinterpret_cast<uint2*>(&g_Xl[idx]) = *reinterpret_cast<uint2*>(l);
}

// ---------------------------------------------------------------------------
// Transpose + convert W: Wqk[1024][2048] / Wv[1024][1024] -> Wt[hi/lo][n][k].
// ---------------------------------------------------------------------------
__global__ void __launch_bounds__(256) cvtW_kernel(
    const float* __restrict__ Wqk, const float* __restrict__ Wv)
{
    __shared__ float s[32][33];
    const int tx = threadIdx.x & 31;
    const int ty = threadIdx.x >> 5;          // 0..7
    const int nTile = blockIdx.x * 32;
    const int kTile = blockIdx.y * 32;

    #pragma unroll
    for (int r = 0; r < 4; r++) {
        int k = kTile + ty + r * 8;
        int n = nTile + tx;
        float v = (n < 2 * OP) ? Wqk[(size_t)k * (2 * OP) + n]
                               : Wv[(size_t)k * OP + (n - 2 * OP)];
        s[ty + r * 8][tx] = v;
    }
    __syncthreads();
    #pragma unroll
    for (int r = 0; r < 4; r++) {
        int n = nTile + ty + r * 8;
        int k = kTile + tx;
        __nv_bfloat16 h, l;
        hilo(s[tx][ty + r * 8], h, l);
        g_Wh[(size_t)n * HIDD + k] = h;
        g_Wl[(size_t)n * HIDD + k] = l;
    }
}

// ---------------------------------------------------------------------------
// MMA / ldmatrix helpers
// ---------------------------------------------------------------------------
#define LDX4(r, a) \
    asm volatile("ldmatrix.sync.aligned.m8n8.x4.shared.b16 {%0,%1,%2,%3}, [%4];" \
        : "=r"((r)[0]), "=r"((r)[1]), "=r"((r)[2]), "=r"((r)[3]) : "r"(a))

#define LDX4T(r, a) \
    asm volatile("ldmatrix.sync.aligned.m8n8.x4.trans.shared.b16 {%0,%1,%2,%3}, [%4];" \
        : "=r"((r)[0]), "=r"((r)[1]), "=r"((r)[2]), "=r"((r)[3]) : "r"(a))

#define MMA16816(c, a, b0_, b1_) \
    asm volatile("mma.sync.aligned.m16n8k16.row.col.f32.bf16.bf16.f32 " \
        "{%0,%1,%2,%3},{%4,%5,%6,%7},{%8,%9},{%0,%1,%2,%3};" \
        : "+f"((c)[0]), "+f"((c)[1]), "+f"((c)[2]), "+f"((c)[3]) \
        : "r"((a)[0]), "r"((a)[1]), "r"((a)[2]), "r"((a)[3]), \
          "r"(b0_), "r"(b1_))

__device__ __forceinline__ uint32_t smem_u32(const void* p) {
    uint32_t a;
    asm("{ .reg .u64 t; cvta.to.shared.u64 t, %1; cvt.u32.u64 %0, t; }"
        : "=r"(a) : "l"(p));
    return a;
}

// ---------------------------------------------------------------------------
// QKV projection on HMMA (m16n8k16 bf16, 2-term split), epilogue emits
// bf16 hi/lo Q (pre-scaled 1/8), K, V in [B,NH,S,HD].
// ---------------------------------------------------------------------------
#define SROW 40   // 32 bf16 row padded to 80B

__device__ __forceinline__ void qkv_store2(int m, int n, float v0, float v1,
                                           const float* bqk, const float* bv)
{
    int b = m >> 11;
    int s = m & (SEQ - 1);
    const float* bias = (n < 2 * OP) ? &bqk[n] : &bv[n - 2 * OP];
    v0 += bias[0]; v1 += bias[1];
    __nv_bfloat16 *bufH, *bufL; int loc;
    if (n < OP)          { bufH = g_Qh; bufL = g_Ql; loc = n;
                           v0 *= 0.125f; v1 *= 0.125f; }
    else if (n < 2 * OP) { bufH = g_Kh; bufL = g_Kl; loc = n - OP; }
    else                 { bufH = g_Vh; bufL = g_Vl; loc = n - 2 * OP; }
    int hh = loc >> 6, dd = loc & 63;
    size_t off = (((size_t)(b * NH + hh)) * SEQ + s) * HD + dd;
    __nv_bfloat16 h0, l0, h1, l1;
    hilo(v0, h0, l0); hilo(v1, h1, l1);
    *reinterpret_cast<uint32_t*>(&bufH[off]) = pk2(h0, h1);
    *reinterpret_cast<uint32_t*>(&bufL[off]) = pk2(l0, l1);
}

__global__ void __launch_bounds__(256, 2) proj3_kernel(
    const float* __restrict__ bqk, const float* __restrict__ bv)
{
    __shared__ __align__(16) __nv_bfloat16 sAh[128 * SROW];
    __shared__ __align__(16) __nv_bfloat16 sAl[128 * SROW];
    __shared__ __align__(16) __nv_bfloat16 sBh[128 * SROW];
    __shared__ __align__(16) __nv_bfloat16 sBl[128 * SROW];

    const int tid  = threadIdx.x;
    const int lane = tid & 31;
    const int wid  = tid >> 5;
    const int warpM = wid & 3;
    const int warpN = wid >> 2;
    const int mBase = blockIdx.y * 128;
    const int nBase = blockIdx.x * 128;

    const uint32_t uAh = smem_u32(sAh), uAl = smem_u32(sAl);
    const uint32_t uBh = smem_u32(sBh), uBl = smem_u32(sBl);

    float acc[2][8][4];
    #pragma unroll
    for (int i = 0; i < 2; i++)
        #pragma unroll
        for (int j = 0; j < 8; j++)
            #pragma unroll
            for (int q = 0; q < 4; q++) acc[i][j][q] = 0.f;

    const uint32_t aRowOff = (uint32_t)(warpM * 32 + (lane & 15)) * (SROW * 2)
                           + (lane >> 4) * 16;
    const uint32_t bRowSel = (uint32_t)((lane >> 4) * 8 + (lane & 7));
    const uint32_t bHalf   = ((lane >> 3) & 1) * 16;

    for (int c = 0; c < 32; ++c) {
        const int k0 = c * 32;
        __syncthreads();
        #pragma unroll
        for (int i = 0; i < 2; i++) {
            int idx = tid + i * 256;
            int row = idx >> 2;
            int cg  = idx & 3;
            int so  = row * SROW + cg * 8;
            size_t ga = (size_t)(mBase + row) * HIDD + k0 + cg * 8;
            size_t gb = (size_t)(nBase + row) * HIDD + k0 + cg * 8;
            *reinterpret_cast<uint4*>(&sAh[so]) = *reinterpret_cast<const uint4*>(&g_Xh[ga]);
            *reinterpret_cast<uint4*>(&sAl[so]) = *reinterpret_cast<const uint4*>(&g_Xl[ga]);
            *reinterpret_cast<uint4*>(&sBh[so]) = *reinterpret_cast<const uint4*>(&g_Wh[gb]);
            *reinterpret_cast<uint4*>(&sBl[so]) = *reinterpret_cast<const uint4*>(&g_Wl[gb]);
        }
        __syncthreads();

        #pragma unroll
        for (int ks = 0; ks < 2; ks++) {
            const uint32_t kOff = ks * 32;
            uint32_t ah[2][4], al[2][4];
            #pragma unroll
            for (int mi = 0; mi < 2; mi++) {
                uint32_t off = aRowOff + (uint32_t)(mi * 16) * (SROW * 2) + kOff;
                LDX4(ah[mi], uAh + off);
                LDX4(al[mi], uAl + off);
            }
            #pragma unroll
            for (int g = 0; g < 4; g++) {
                uint32_t nrow = (uint32_t)(warpN * 64 + g * 16) + bRowSel;
                uint32_t off = nrow * (SROW * 2) + kOff + bHalf;
                uint32_t bh[4], bl[4];
                LDX4(bh, uBh + off);
                LDX4(bl, uBl + off);
                #pragma unroll
                for (int mi = 0; mi < 2; mi++) {
                    MMA16816(acc[mi][2 * g],     ah[mi], bh[0], bh[1]);
                    MMA16816(acc[mi][2 * g],     ah[mi], bl[0], bl[1]);
                    MMA16816(acc[mi][2 * g],     al[mi], bh[0], bh[1]);
                    MMA16816(acc[mi][2 * g + 1], ah[mi], bh[2], bh[3]);
                    MMA16816(acc[mi][2 * g + 1], ah[mi], bl[2], bl[3]);
                    MMA16816(acc[mi][2 * g + 1], al[mi], bh[2], bh[3]);
                }
            }
        }
    }

    const int mW = mBase + warpM * 32 + (lane >> 2);
    const int nW = nBase + warpN * 64 + (lane & 3) * 2;
    #pragma unroll
    for (int mi = 0; mi < 2; mi++) {
        int r0 = mW + mi * 16;
        #pragma unroll
        for (int g = 0; g < 8; g++) {
            int col = nW + g * 8;
            qkv_store2(r0,     col, acc[mi][g][0], acc[mi][g][1], bqk, bv);
            qkv_store2(r0 + 8, col, acc[mi][g][2], acc[mi][g][3], bqk, bv);
        }
    }
}

// ---------------------------------------------------------------------------
// Causal flash attention on HMMA, split-bf16 exact (Q,K,V,P all hi/lo split).
// QT=128 per CTA, KT=64, 8 warps x 16 q-rows (warp-local softmax).
// ---------------------------------------------------------------------------
#define QROW 72                  // 64 bf16 row padded to 144B
#define AT_QH 0
#define AT_QL (128*QROW*2)       // 18432
#define AT_KH (2*128*QROW*2)     // 36864
#define AT_KL (AT_KH + 64*QROW*2)
#define AT_VH (AT_KL + 64*QROW*2)
#define AT_VL (AT_VH + 64*QROW*2)
#define AT_SMEM (AT_VL + 64*QROW*2)   // 73728 bytes

__global__ void __launch_bounds__(256, 2) attn2_kernel(float* __restrict__ out)
{
    extern __shared__ char sm[];
    const uint32_t sb = smem_u32(sm);

    const int tid  = threadIdx.x;
    const int lane = tid & 31;
    const int wid  = tid >> 5;           // 0..7
    const int qt = gridDim.x - 1 - blockIdx.x;   // heavy tiles first
    const int h  = blockIdx.y;
    const int b  = blockIdx.z;
    const size_t headBase = ((size_t)(b * NH + h)) * SEQ * HD;
    const int qBase = qt * 128;

    // load Q hi/lo (128 x 64)
    #pragma unroll
    for (int i = 0; i < 4; i++) {
        int idx = tid + i * 256;
        int row = idx >> 3, c8 = (idx & 7) * 8;
        size_t g = headBase + (size_t)(qBase + row) * HD + c8;
        uint32_t so = (uint32_t)(row * QROW + c8) * 2;
        *reinterpret_cast<uint4*>(sm + AT_QH + so) = *reinterpret_cast<const uint4*>(&g_Qh[g]);
        *reinterpret_cast<uint4*>(sm + AT_QL + so) = *reinterpret_cast<const uint4*>(&g_Ql[g]);
    }
    __syncthreads();

    // Q fragments, persistent in registers
    uint32_t qh[4][4], ql[4][4];
    const uint32_t aOff = (uint32_t)(wid * 16 + (lane & 15)) * (QROW * 2)
                        + (lane >> 4) * 16;
    #pragma unroll
    for (int ks = 0; ks < 4; ks++) {
        LDX4(qh[ks], sb + AT_QH + aOff + ks * 32);
        LDX4(ql[ks], sb + AT_QL + aOff + ks * 32);
    }

    float o[8][4];
    #pragma unroll
    for (int g = 0; g < 8; g++)
        #pragma unroll
        for (int q = 0; q < 4; q++) o[g][q] = 0.f;
    float m0 = -1e30f, m1 = -1e30f, rl0 = 0.f, rl1 = 0.f;

    const int qW = qBase + wid * 16;
    const int numK = (qBase + 128) / 64;
    const uint32_t bOff = (uint32_t)((lane >> 4) * 8 + (lane & 7)) * (QROW * 2)
                        + ((lane >> 3) & 1) * 16;
    const uint32_t vOff = (uint32_t)(lane & 15) * (QROW * 2) + (lane >> 4) * 16;

    for (int kt = 0; kt < numK; kt++) {
        const int kBase = kt * 64;
        __syncthreads();
        #pragma unroll
        for (int i = 0; i < 2; i++) {
            int idx = tid + i * 256;
            int row = idx >> 3, c8 = (idx & 7) * 8;
            size_t g = headBase + (size_t)(kBase + row) * HD + c8;
            uint32_t so = (uint32_t)(row * QROW + c8) * 2;
            *reinterpret_cast<uint4*>(sm + AT_KH + so) = *reinterpret_cast<const uint4*>(&g_Kh[g]);
            *reinterpret_cast<uint4*>(sm + AT_KL + so) = *reinterpret_cast<const uint4*>(&g_Kl[g]);
            *reinterpret_cast<uint4*>(sm + AT_VH + so) = *reinterpret_cast<const uint4*>(&g_Vh[g]);
            *reinterpret_cast<uint4*>(sm + AT_VL + so) = *reinterpret_cast<const uint4*>(&g_Vl[g]);
        }
        __syncthreads();

        if (kBase > qW + 15) continue;   // fully masked for this warp

        // S = Q K^T (3-term split)
        float s[8][4];
        #pragma unroll
        for (int g = 0; g < 8; g++)
            #pragma unroll
            for (int q = 0; q < 4; q++) s[g][q] = 0.f;

        #pragma unroll
        for (int ks = 0; ks < 4; ks++) {
            #pragma unroll
            for (int nb = 0; nb < 4; nb++) {
                uint32_t addr = (uint32_t)(nb * 16) * (QROW * 2) + bOff + ks * 32;
                uint32_t bh[4], bl[4];
                LDX4(bh, sb + AT_KH + addr);
                LDX4(bl, sb + AT_KL + addr);
                MMA16816(s[2 * nb],     qh[ks], bh[0], bh[1]);
                MMA16816(s[2 * nb],     qh[ks], bl[0], bl[1]);
                MMA16816(s[2 * nb],     ql[ks], bh[0], bh[1]);
                MMA16816(s[2 * nb + 1], qh[ks], bh[2], bh[3]);
                MMA16816(s[2 * nb + 1], qh[ks], bl[2], bl[3]);
                MMA16816(s[2 * nb + 1], ql[ks], bh[2], bh[3]);
            }
        }

        // causal mask (scores already scaled: Q pre-multiplied by 1/8)
        const int r0 = qW + (lane >> 2);
        const int c0 = kBase + (lane & 3) * 2;
        if (kBase + 63 > qW) {
            #pragma unroll
            for (int g = 0; g < 8; g++) {
                int c = c0 + g * 8;
                if (c     > r0)     s[g][0] = -1e30f;
                if (c + 1 > r0)     s[g][1] = -1e30f;
                if (c     > r0 + 8) s[g][2] = -1e30f;
                if (c + 1 > r0 + 8) s[g][3] = -1e30f;
            }
        }

        // warp-local online softmax (rows r0 and r0+8)
        float mx0 = -1e30f, mx1 = -1e30f;
        #pragma unroll
        for (int g = 0; g < 8; g++) {
            mx0 = fmaxf(mx0, fmaxf(s[g][0], s[g][1]));
            mx1 = fmaxf(mx1, fmaxf(s[g][2], s[g][3]));
        }
        mx0 = fmaxf(mx0, __shfl_xor_sync(0xFFFFFFFFu, mx0, 1));
        mx0 = fmaxf(mx0, __shfl_xor_sync(0xFFFFFFFFu, mx0, 2));
        mx1 = fmaxf(mx1, __shfl_xor_sync(0xFFFFFFFFu, mx1, 1));
        mx1 = fmaxf(mx1, __shfl_xor_sync(0xFFFFFFFFu, mx1, 2));

        float mn0 = fmaxf(m0, mx0), mn1 = fmaxf(m1, mx1);
        float a0 = __expf(m0 - mn0), a1 = __expf(m1 - mn1);
        m0 = mn0; m1 = mn1;

        float sl0 = 0.f, sl1 = 0.f;
        uint32_t pah[8], pbh[8], pal[8], pbl[8];
        #pragma unroll
        for (int g = 0; g < 8; g++) {
            float p0 = __expf(s[g][0] - mn0);
            float p1 = __expf(s[g][1] - mn0);
            float p2 = __expf(s[g][2] - mn1);
            float p3 = __expf(s[g][3] - mn1);
            sl0 += p0 + p1; sl1 += p2 + p3;
            __nv_bfloat16 h0, lo0, h1, lo1;
            hilo(p0, h0, lo0); hilo(p1, h1, lo1);
            pah[g] = pk2(h0, h1); pal[g] = pk2(lo0, lo1);
            hilo(p2, h0, lo0); hilo(p3, h1, lo1);
            pbh[g] = pk2(h0, h1); pbl[g] = pk2(lo0, lo1);
        }
        sl0 += __shfl_xor_sync(0xFFFFFFFFu, sl0, 1);
        sl0 += __shfl_xor_sync(0xFFFFFFFFu, sl0, 2);
        sl1 += __shfl_xor_sync(0xFFFFFFFFu, sl1, 1);
        sl1 += __shfl_xor_sync(0xFFFFFFFFu, sl1, 2);
        rl0 = rl0 * a0 + sl0;
        rl1 = rl1 * a1 + sl1;

        #pragma unroll
        for (int g = 0; g < 8; g++) {
            o[g][0] *= a0; o[g][1] *= a0;
            o[g][2] *= a1; o[g][3] *= a1;
        }

        // O += P V (3-term split), V B-fragments via ldmatrix.trans
        #pragma unroll
        for (int ks = 0; ks < 4; ks++) {
            uint32_t Ah[4] = {pah[2 * ks], pbh[2 * ks], pah[2 * ks + 1], pbh[2 * ks + 1]};
            uint32_t Al[4] = {pal[2 * ks], pbl[2 * ks], pal[2 * ks + 1], pbl[2 * ks + 1]};
            #pragma unroll
            for (int db = 0; db < 4; db++) {
                uint32_t addr = (uint32_t)(ks * 16) * (QROW * 2) + db * 32 + vOff;
                uint32_t vh[4], vl[4];
                LDX4T(vh, sb + AT_VH + addr);
                LDX4T(vl, sb + AT_VL + addr);
                MMA16816(o[2 * db],     Ah, vh[0], vh[1]);
                MMA16816(o[2 * db],     Ah, vl[0], vl[1]);
                MMA16816(o[2 * db],     Al, vh[0], vh[1]);
                MMA16816(o[2 * db + 1], Ah, vh[2], vh[3]);
                MMA16816(o[2 * db + 1], Ah, vl[2], vl[3]);
                MMA16816(o[2 * db + 1], Al, vh[2], vh[3]);
            }
        }
    }

    // epilogue: normalize, write fp32
    const float i0 = 1.f / rl0, i1 = 1.f / rl1;
    const int s0 = qBase + wid * 16 + (lane >> 2);
    const int dB = (lane & 3) * 2;
    #pragma unroll
    for (int g = 0; g < 8; g++) {
        int d = h * HD + g * 8 + dB;
        *reinterpret_cast<float2*>(&out[((size_t)b * SEQ + s0) * OP + d]) =
            make_float2(o[g][0] * i0, o[g][1] * i0);
        *reinterpret_cast<float2*>(&out[((size_t)b * SEQ + s0 + 8) * OP + d]) =
            make_float2(o[g][2] * i1, o[g][3] * i1);
    }
}

// ---------------------------------------------------------------------------
extern "C" void kernel_launch(void* const* d_in, const int* in_sizes, int n_in,
                              void* d_out, int out_size)
{
    const float* X   = (const float*)d_in[0];
    const float* Wqk = (const float*)d_in[1];
    const float* bqk = (const float*)d_in[2];
    const float* Wv  = (const float*)d_in[3];
    const float* bv  = (const float*)d_in[4];
    float* out = (float*)d_out;

    (void)in_sizes; (void)n_in; (void)out_size;

    cvtX_kernel<<<MTOT * HIDD / 1024, 256>>>(X);
    cvtW_kernel<<<dim3(NTOT / 32, HIDD / 32), 256>>>(Wqk, Wv);

    dim3 g1(NTOT / 128, MTOT / 128);   // (24, 32)
    proj3_kernel<<<g1, 256>>>(bqk, bv);

    cudaFuncSetAttribute(attn2_kernel,
                         cudaFuncAttributeMaxDynamicSharedMemorySize, AT_SMEM);
    dim3 g2(SEQ / 128, NH, BATCH);     // (16, 16, 2)
    attn2_kernel<<<g2, 256, AT_SMEM>>>(out);
}